// round 2
// baseline (speedup 1.0000x reference)
#include <cuda_runtime.h>
#include <cuda_bf16.h>
#include <math.h>

// ---------------- problem constants ----------------
#define BB 32
#define SS 197
#define EE 768
#define HH 12
#define DHH 64
#define FF_ 2048
#define LL 4
#define CC 1000
#define BS (BB * SS)   // 6304
#define LN_EPS 1e-5f

// ---------------- scratch (device globals; allocation-free rule) ------------
__device__ float g_h   [BS * EE];          // hidden state
__device__ float g_xn  [BS * EE];          // layernorm output
__device__ float g_q   [HH * BS * DHH];    // [h][b*s][d]
__device__ float g_k   [HH * BS * DHH];
__device__ float g_v   [HH * BS * DHH];
__device__ float g_att [BB * HH * SS * SS];
__device__ float g_o   [BS * EE];          // concat-head output [bs][h*64+d]
__device__ float g_res1[BS * EE];
__device__ float g_ff  [BS * FF_];

// ---------------- layernorm: one block per row (E=768) ----------------------
__global__ void layernorm_kernel(const float* __restrict__ x,
                                 const float* __restrict__ w,
                                 const float* __restrict__ b,
                                 float* __restrict__ out) {
    int row = blockIdx.x;
    const float* xr = x + (long long)row * EE;
    float* orow = out + (long long)row * EE;
    int tid = threadIdx.x;  // 256

    float s = 0.f, s2 = 0.f;
    #pragma unroll
    for (int i = tid; i < EE; i += 256) {
        float v = xr[i];
        s += v; s2 += v * v;
    }
    __shared__ float rs[256], rs2[256];
    rs[tid] = s; rs2[tid] = s2;
    __syncthreads();
    for (int st = 128; st > 0; st >>= 1) {
        if (tid < st) { rs[tid] += rs[tid + st]; rs2[tid] += rs2[tid + st]; }
        __syncthreads();
    }
    float mu = rs[0] * (1.f / EE);
    float var = rs2[0] * (1.f / EE) - mu * mu;
    float rstd = rsqrtf(var + LN_EPS);
    #pragma unroll
    for (int i = tid; i < EE; i += 256) {
        orow[i] = (xr[i] - mu) * rstd * w[i] + b[i];
    }
}

// ---------------- attention softmax: one block per row (len 197) -------------
__global__ void att_softmax_kernel(float* __restrict__ att) {
    long long row = blockIdx.x;
    float* r = att + row * (long long)SS;
    int tid = threadIdx.x;  // 128
    __shared__ float red[128];

    float m = -1e30f;
    for (int i = tid; i < SS; i += 128) m = fmaxf(m, r[i]);
    red[tid] = m; __syncthreads();
    for (int st = 64; st > 0; st >>= 1) {
        if (tid < st) red[tid] = fmaxf(red[tid], red[tid + st]);
        __syncthreads();
    }
    m = red[0];
    __syncthreads();

    float sum = 0.f;
    for (int i = tid; i < SS; i += 128) {
        float e = expf(r[i] - m);
        r[i] = e; sum += e;
    }
    red[tid] = sum; __syncthreads();
    for (int st = 64; st > 0; st >>= 1) {
        if (tid < st) red[tid] += red[tid + st];
        __syncthreads();
    }
    float inv = 1.f / red[0];
    for (int i = tid; i < SS; i += 128) r[i] *= inv;
}

// ---------------- generic batched SGEMM (64x64x16, 256 thr, 4x4/thread) -----
// EPI: 0 -> C = alpha*acc
//      1 -> C = gelu(acc + bias[n])            (exact gelu)
//      2 -> C = acc + D[m,n]                   (residual)
//      3 -> C = acc + bias[n] + D[m,n]         (bias + residual)
// TRANSB: B accessed as B[n*ldb + k] (A @ B^T)
// batch: z = zo*innerB + zi ; ptr += zo*s?1 + zi*s?2 ; D shares C offsets.
template <int EPI, bool TRANSB>
__global__ __launch_bounds__(256)
void sgemm_kernel(const float* __restrict__ A, const float* __restrict__ Bm,
                  float* __restrict__ Cm,
                  const float* __restrict__ bias, const float* __restrict__ Dm,
                  int M, int N, int K, int lda, int ldb, int ldc,
                  long long sA1, long long sA2, long long sB1, long long sB2,
                  long long sC1, long long sC2, int innerB, float alpha) {
    int zo = blockIdx.z / innerB, zi = blockIdx.z % innerB;
    A  += zo * sA1 + zi * sA2;
    Bm += zo * sB1 + zi * sB2;
    long long coff = zo * sC1 + zi * sC2;
    Cm += coff;
    const float* Dp = (EPI == 2 || EPI == 3) ? (Dm + coff) : nullptr;

    const int m0 = blockIdx.y * 64, n0 = blockIdx.x * 64;

    __shared__ __align__(16) float As[16][64];
    __shared__ __align__(16) float Bs[16][64];

    int tid = threadIdx.x;
    int tx = tid & 15, ty = tid >> 4;

    float acc[4][4] = {};

    for (int k0 = 0; k0 < K; k0 += 16) {
        // A tile: 64 rows x 16 cols  -> As[k][m]
        #pragma unroll
        for (int j = 0; j < 4; j++) {
            int idx = tid + j * 256;
            int ar = idx >> 4, ac = idx & 15;
            int gm = m0 + ar, gk = k0 + ac;
            As[ac][ar] = (gm < M && gk < K) ? A[(long long)gm * lda + gk] : 0.f;
        }
        // B tile -> Bs[k][n]
        #pragma unroll
        for (int j = 0; j < 4; j++) {
            int idx = tid + j * 256;
            if (!TRANSB) {
                int br = idx >> 6, bc = idx & 63;
                int gk = k0 + br, gn = n0 + bc;
                Bs[br][bc] = (gk < K && gn < N) ? Bm[(long long)gk * ldb + gn] : 0.f;
            } else {
                int bn = idx >> 4, bk = idx & 15;
                int gn = n0 + bn, gk = k0 + bk;
                Bs[bk][bn] = (gn < N && gk < K) ? Bm[(long long)gn * ldb + gk] : 0.f;
            }
        }
        __syncthreads();
        #pragma unroll
        for (int kk = 0; kk < 16; kk++) {
            float4 a4 = *reinterpret_cast<const float4*>(&As[kk][ty * 4]);
            float4 b4 = *reinterpret_cast<const float4*>(&Bs[kk][tx * 4]);
            float av[4] = {a4.x, a4.y, a4.z, a4.w};
            float bv[4] = {b4.x, b4.y, b4.z, b4.w};
            #pragma unroll
            for (int i = 0; i < 4; i++)
                #pragma unroll
                for (int j = 0; j < 4; j++)
                    acc[i][j] += av[i] * bv[j];
        }
        __syncthreads();
    }

    #pragma unroll
    for (int i = 0; i < 4; i++) {
        int m = m0 + ty * 4 + i;
        if (m >= M) continue;
        #pragma unroll
        for (int j = 0; j < 4; j++) {
            int n = n0 + tx * 4 + j;
            if (n >= N) continue;
            float v = acc[i][j] * alpha;
            if (EPI == 1) {
                v += bias[n];
                v = 0.5f * v * (1.f + erff(v * 0.70710678118654752f));
            } else if (EPI == 2) {
                v += Dp[(long long)m * ldc + n];
            } else if (EPI == 3) {
                v += bias[n] + Dp[(long long)m * ldc + n];
            }
            Cm[(long long)m * ldc + n] = v;
        }
    }
}

// ---------------- classifier + final softmax: one block per batch ------------
__global__ void classifier_kernel(const float* __restrict__ hbuf,
                                  const float* __restrict__ Wc,
                                  const float* __restrict__ bc,
                                  float* __restrict__ out) {
    int b = blockIdx.x;
    int tid = threadIdx.x;  // 256
    __shared__ float xs[EE];
    __shared__ float lg[CC];
    __shared__ float red[256];

    const float* xr = hbuf + (long long)b * SS * EE;  // row s=0
    for (int i = tid; i < EE; i += 256) xs[i] = xr[i];
    __syncthreads();

    for (int c = tid; c < CC; c += 256) {
        float acc = bc[c];
        for (int e = 0; e < EE; e++) acc += xs[e] * Wc[(long long)e * CC + c];
        lg[c] = acc;
    }
    __syncthreads();

    float m = -1e30f;
    for (int c = tid; c < CC; c += 256) m = fmaxf(m, lg[c]);
    red[tid] = m; __syncthreads();
    for (int st = 128; st > 0; st >>= 1) {
        if (tid < st) red[tid] = fmaxf(red[tid], red[tid + st]);
        __syncthreads();
    }
    m = red[0];
    __syncthreads();

    float sum = 0.f;
    for (int c = tid; c < CC; c += 256) {
        float e = expf(lg[c] - m);
        lg[c] = e; sum += e;
    }
    red[tid] = sum; __syncthreads();
    for (int st = 128; st > 0; st >>= 1) {
        if (tid < st) red[tid] += red[tid + st];
        __syncthreads();
    }
    float inv = 1.f / red[0];
    for (int c = tid; c < CC; c += 256)
        out[(long long)b * CC + c] = lg[c] * inv;
}

// ---------------- host orchestration ----------------------------------------
extern "C" void kernel_launch(void* const* d_in, const int* in_sizes, int n_in,
                              void* d_out, int out_size) {
    const float* x     = (const float*)d_in[0];
    const float* Wk    = (const float*)d_in[1];
    const float* Wq    = (const float*)d_in[2];
    const float* Wv    = (const float*)d_in[3];
    const float* Wconv = (const float*)d_in[4];
    const float* ln1_w = (const float*)d_in[5];
    const float* ln1_b = (const float*)d_in[6];
    const float* ln2_w = (const float*)d_in[7];
    const float* ln2_b = (const float*)d_in[8];
    const float* W1    = (const float*)d_in[9];
    const float* b1    = (const float*)d_in[10];
    const float* W2    = (const float*)d_in[11];
    const float* b2    = (const float*)d_in[12];
    const float* Wc    = (const float*)d_in[13];
    const float* bc    = (const float*)d_in[14];
    float* out = (float*)d_out;

    float *ph, *pxn, *pq, *pk, *pv, *patt, *po, *pres1, *pff;
    cudaGetSymbolAddress((void**)&ph,    g_h);
    cudaGetSymbolAddress((void**)&pxn,   g_xn);
    cudaGetSymbolAddress((void**)&pq,    g_q);
    cudaGetSymbolAddress((void**)&pk,    g_k);
    cudaGetSymbolAddress((void**)&pv,    g_v);
    cudaGetSymbolAddress((void**)&patt,  g_att);
    cudaGetSymbolAddress((void**)&po,    g_o);
    cudaGetSymbolAddress((void**)&pres1, g_res1);
    cudaGetSymbolAddress((void**)&pff,   g_ff);

    cudaMemcpyAsync(ph, x, sizeof(float) * (size_t)BS * EE,
                    cudaMemcpyDeviceToDevice);

    const float inv_scale = 1.f / sqrtf((float)SS);
    const int MT = (BS + 63) / 64;  // 99 row tiles

    for (int l = 0; l < LL; l++) {
        const float* Wq_l = Wq + (long long)l * HH * EE * DHH;
        const float* Wk_l = Wk + (long long)l * HH * EE * DHH;
        const float* Wv_l = Wv + (long long)l * HH * EE * DHH;
        const float* Wcv_l = Wconv + (long long)l * EE * EE;
        const float* W1_l = W1 + (long long)l * EE * FF_;
        const float* b1_l = b1 + (long long)l * FF_;
        const float* W2_l = W2 + (long long)l * FF_ * EE;
        const float* b2_l = b2 + (long long)l * EE;

        // LN1
        layernorm_kernel<<<BS, 256>>>(ph, ln1_w + l * EE, ln1_b + l * EE, pxn);

        // Q,K,V: per-head GEMM  [BS x 768] @ [768 x 64]  (z over heads)
        {
            dim3 g(1, MT, HH);
            sgemm_kernel<0, false><<<g, 256>>>(pxn, Wq_l, pq, nullptr, nullptr,
                BS, DHH, EE, EE, DHH, DHH,
                0, 0, 0, (long long)EE * DHH,
                0, (long long)BS * DHH, HH, 1.f);
            sgemm_kernel<0, false><<<g, 256>>>(pxn, Wk_l, pk, nullptr, nullptr,
                BS, DHH, EE, EE, DHH, DHH,
                0, 0, 0, (long long)EE * DHH,
                0, (long long)BS * DHH, HH, 1.f);
            sgemm_kernel<0, false><<<g, 256>>>(pxn, Wv_l, pv, nullptr, nullptr,
                BS, DHH, EE, EE, DHH, DHH,
                0, 0, 0, (long long)EE * DHH,
                0, (long long)BS * DHH, HH, 1.f);
        }

        // scores = Q @ K^T * inv_scale   (batched over b,h)
        {
            dim3 g(4, 4, BB * HH);
            sgemm_kernel<0, true><<<g, 256>>>(pq, pk, patt, nullptr, nullptr,
                SS, SS, DHH, DHH, DHH, SS,
                (long long)SS * DHH, (long long)BS * DHH,
                (long long)SS * DHH, (long long)BS * DHH,
                (long long)HH * SS * SS, (long long)SS * SS, HH, inv_scale);
        }

        // softmax over last dim
        att_softmax_kernel<<<BB * HH * SS, 128>>>(patt);

        // O = att @ V  (write directly into concat-head layout [bs][h*64+d])
        {
            dim3 g(1, 4, BB * HH);
            sgemm_kernel<0, false><<<g, 256>>>(patt, pv, po, nullptr, nullptr,
                SS, DHH, SS, SS, DHH, EE,
                (long long)HH * SS * SS, (long long)SS * SS,
                (long long)SS * DHH, (long long)BS * DHH,
                (long long)SS * EE, (long long)DHH, HH, 1.f);
        }

        // res1 = O @ Wconv + h
        {
            dim3 g(EE / 64, MT, 1);
            sgemm_kernel<2, false><<<g, 256>>>(po, Wcv_l, pres1, nullptr, ph,
                BS, EE, EE, EE, EE, EE,
                0, 0, 0, 0, 0, 0, 1, 1.f);
        }

        // LN2
        layernorm_kernel<<<BS, 256>>>(pres1, ln2_w + l * EE, ln2_b + l * EE, pxn);

        // FF1 = gelu(xn2 @ W1 + b1)
        {
            dim3 g(FF_ / 64, MT, 1);
            sgemm_kernel<1, false><<<g, 256>>>(pxn, W1_l, pff, b1_l, nullptr,
                BS, FF_, EE, EE, FF_, FF_,
                0, 0, 0, 0, 0, 0, 1, 1.f);
        }

        // h = FF1 @ W2 + b2 + res1
        {
            dim3 g(EE / 64, MT, 1);
            sgemm_kernel<3, false><<<g, 256>>>(pff, W2_l, ph, b2_l, pres1,
                BS, EE, FF_, FF_, EE, EE,
                0, 0, 0, 0, 0, 0, 1, 1.f);
        }
    }

    // classifier + softmax
    classifier_kernel<<<BB, 256>>>(ph, Wc, bc, out);
}

// round 3
// speedup vs baseline: 1.7415x; 1.7415x over previous
#include <cuda_runtime.h>
#include <cuda_bf16.h>
#include <mma.h>
#include <math.h>

using namespace nvcuda;

// ---------------- problem constants ----------------
#define BB 32
#define SS 197
#define EE 768
#define HH 12
#define DHH 64
#define FF_ 2048
#define LL 4
#define CC 1000
#define BS (BB * SS)   // 6304
#define LN_EPS 1e-5f

// ---------------- scratch (device globals; allocation-free rule) ------------
__device__ float g_h   [BS * EE];
__device__ float g_xn  [BS * EE];
__device__ float g_q   [HH * BS * DHH];
__device__ float g_k   [HH * BS * DHH];
__device__ float g_v   [HH * BS * DHH];
__device__ float g_att [BB * HH * SS * SS];
__device__ float g_o   [BS * EE];
__device__ float g_res1[BS * EE];
__device__ float g_ff  [BS * FF_];

// ---------------- layernorm: one block per row (E=768) ----------------------
__global__ void layernorm_kernel(const float* __restrict__ x,
                                 const float* __restrict__ w,
                                 const float* __restrict__ b,
                                 float* __restrict__ out) {
    int row = blockIdx.x;
    const float* xr = x + (long long)row * EE;
    float* orow = out + (long long)row * EE;
    int tid = threadIdx.x;  // 256

    float s = 0.f, s2 = 0.f;
    #pragma unroll
    for (int i = tid; i < EE; i += 256) {
        float v = xr[i];
        s += v; s2 += v * v;
    }
    __shared__ float rs[256], rs2[256];
    rs[tid] = s; rs2[tid] = s2;
    __syncthreads();
    for (int st = 128; st > 0; st >>= 1) {
        if (tid < st) { rs[tid] += rs[tid + st]; rs2[tid] += rs2[tid + st]; }
        __syncthreads();
    }
    float mu = rs[0] * (1.f / EE);
    float var = rs2[0] * (1.f / EE) - mu * mu;
    float rstd = rsqrtf(var + LN_EPS);
    #pragma unroll
    for (int i = tid; i < EE; i += 256) {
        orow[i] = (xr[i] - mu) * rstd * w[i] + b[i];
    }
}

// ---------------- attention softmax: one block per row (len 197) -------------
__global__ void att_softmax_kernel(float* __restrict__ att) {
    long long row = blockIdx.x;
    float* r = att + row * (long long)SS;
    int tid = threadIdx.x;  // 128
    __shared__ float red[128];

    float m = -1e30f;
    for (int i = tid; i < SS; i += 128) m = fmaxf(m, r[i]);
    red[tid] = m; __syncthreads();
    for (int st = 64; st > 0; st >>= 1) {
        if (tid < st) red[tid] = fmaxf(red[tid], red[tid + st]);
        __syncthreads();
    }
    m = red[0];
    __syncthreads();

    float sum = 0.f;
    for (int i = tid; i < SS; i += 128) {
        float e = expf(r[i] - m);
        r[i] = e; sum += e;
    }
    red[tid] = sum; __syncthreads();
    for (int st = 64; st > 0; st >>= 1) {
        if (tid < st) red[tid] += red[tid + st];
        __syncthreads();
    }
    float inv = 1.f / red[0];
    for (int i = tid; i < SS; i += 128) r[i] *= inv;
}

// ---------------- TF32 tensor-core GEMM (128x64 tile, BK=32, 256 thr) -------
// EPI: 0 -> C = alpha*acc
//      1 -> C = gelu(acc + bias[n])            (exact gelu)
//      2 -> C = acc + D[m,n]                   (residual)
//      3 -> C = acc + bias[n] + D[m,n]         (bias + residual)
// TRANSB: logical B[k][n] is stored as Bg[n][k] (A @ B^T); transposed during
//         the gmem->smem copy so the MMA path is identical.
// batch: z = zo*innerB + zi ; ptr += zo*s?1 + zi*s?2 ; D shares C offsets.
#define BM 128
#define BN 64
#define BK 32
#define LDA_S 36   // BK + 4  (mult of 4 for wmma)
#define LDB_S 68   // BN + 4
#define LDS_S 36   // staging ld

template <int EPI, bool TRANSB>
__global__ __launch_bounds__(256)
void tc_gemm_kernel(const float* __restrict__ A, const float* __restrict__ Bm,
                    float* __restrict__ Cm,
                    const float* __restrict__ bias, const float* __restrict__ Dm,
                    int M, int N, int K, int lda, int ldb, int ldc,
                    long long sA1, long long sA2, long long sB1, long long sB2,
                    long long sC1, long long sC2, int innerB, float alpha) {
    int zo = blockIdx.z / innerB, zi = blockIdx.z % innerB;
    A  += zo * sA1 + zi * sA2;
    Bm += zo * sB1 + zi * sB2;
    long long coff = zo * sC1 + zi * sC2;
    Cm += coff;
    const float* Dp = (EPI == 2 || EPI == 3) ? (Dm + coff) : nullptr;

    const int m0 = blockIdx.y * BM, n0 = blockIdx.x * BN;

    // union: [ As 128x36 | Bs 32x68 ] reused as staging [8 warps x 32x36]
    __shared__ __align__(16) float smem[8 * 32 * LDS_S];  // 9216 floats
    float* As = smem;                 // As[m][k], ld = LDA_S
    float* Bsm = smem + BM * LDA_S;   // Bs[k][n], ld = LDB_S

    int tid = threadIdx.x;
    int wid = tid >> 5, lane = tid & 31;
    int wm = wid & 3, wn = wid >> 2;          // 4 x 2 warp grid, 32x32 each

    wmma::fragment<wmma::accumulator, 16, 16, 8, float> acc[2][2];
    #pragma unroll
    for (int i = 0; i < 2; i++)
        #pragma unroll
        for (int j = 0; j < 2; j++)
            wmma::fill_fragment(acc[i][j], 0.f);

    for (int k0 = 0; k0 < K; k0 += BK) {
        // A tile: BM x BK  (coalesced along k)
        #pragma unroll
        for (int it = 0; it < (BM * BK) / 256; it++) {
            int i = tid + it * 256;
            int m = i >> 5, k = i & 31;
            int gm = m0 + m, gk = k0 + k;
            As[m * LDA_S + k] =
                (gm < M && gk < K) ? A[(long long)gm * lda + gk] : 0.f;
        }
        // B tile: BK x BN
        #pragma unroll
        for (int it = 0; it < (BK * BN) / 256; it++) {
            int i = tid + it * 256;
            if (!TRANSB) {
                int k = i >> 6, n = i & 63;
                int gk = k0 + k, gn = n0 + n;
                Bsm[k * LDB_S + n] =
                    (gk < K && gn < N) ? Bm[(long long)gk * ldb + gn] : 0.f;
            } else {
                int n = i >> 5, k = i & 31;
                int gn = n0 + n, gk = k0 + k;
                Bsm[k * LDB_S + n] =
                    (gn < N && gk < K) ? Bm[(long long)gn * ldb + gk] : 0.f;
            }
        }
        __syncthreads();

        #pragma unroll
        for (int ks = 0; ks < BK / 8; ks++) {
            wmma::fragment<wmma::matrix_a, 16, 16, 8, wmma::precision::tf32,
                           wmma::row_major> af[2];
            wmma::fragment<wmma::matrix_b, 16, 16, 8, wmma::precision::tf32,
                           wmma::row_major> bf[2];
            #pragma unroll
            for (int i = 0; i < 2; i++) {
                wmma::load_matrix_sync(
                    af[i], As + (wm * 32 + i * 16) * LDA_S + ks * 8, LDA_S);
                #pragma unroll
                for (int t = 0; t < af[i].num_elements; t++)
                    af[i].x[t] = wmma::__float_to_tf32(af[i].x[t]);
            }
            #pragma unroll
            for (int j = 0; j < 2; j++) {
                wmma::load_matrix_sync(
                    bf[j], Bsm + (ks * 8) * LDB_S + wn * 32 + j * 16, LDB_S);
                #pragma unroll
                for (int t = 0; t < bf[j].num_elements; t++)
                    bf[j].x[t] = wmma::__float_to_tf32(bf[j].x[t]);
            }
            #pragma unroll
            for (int i = 0; i < 2; i++)
                #pragma unroll
                for (int j = 0; j < 2; j++)
                    wmma::mma_sync(acc[i][j], af[i], bf[j], acc[i][j]);
        }
        __syncthreads();
    }

    // ---- epilogue: stage through smem (handles boundaries + fusions) -------
    float* ws = smem + wid * (32 * LDS_S);
    #pragma unroll
    for (int i = 0; i < 2; i++)
        #pragma unroll
        for (int j = 0; j < 2; j++)
            wmma::store_matrix_sync(ws + (i * 16) * LDS_S + j * 16, acc[i][j],
                                    LDS_S, wmma::mem_row_major);
    __syncwarp();

    int mbase = m0 + wm * 32;
    int n = n0 + wn * 32 + lane;
    if (n < N) {
        float bn_ = (EPI == 1 || EPI == 3) ? bias[n] : 0.f;
        #pragma unroll 4
        for (int r = 0; r < 32; r++) {
            int m = mbase + r;
            if (m >= M) break;
            float v = ws[r * LDS_S + lane] * alpha;
            if (EPI == 1) {
                v += bn_;
                v = 0.5f * v * (1.f + erff(v * 0.70710678118654752f));
            } else if (EPI == 2) {
                v += Dp[(long long)m * ldc + n];
            } else if (EPI == 3) {
                v += bn_ + Dp[(long long)m * ldc + n];
            }
            Cm[(long long)m * ldc + n] = v;
        }
    }
}

// ---------------- classifier + final softmax: one block per batch ------------
__global__ void classifier_kernel(const float* __restrict__ hbuf,
                                  const float* __restrict__ Wc,
                                  const float* __restrict__ bc,
                                  float* __restrict__ out) {
    int b = blockIdx.x;
    int tid = threadIdx.x;  // 256
    __shared__ float xs[EE];
    __shared__ float lg[CC];
    __shared__ float red[256];

    const float* xr = hbuf + (long long)b * SS * EE;  // row s=0
    for (int i = tid; i < EE; i += 256) xs[i] = xr[i];
    __syncthreads();

    for (int c = tid; c < CC; c += 256) {
        float acc = bc[c];
        for (int e = 0; e < EE; e++) acc += xs[e] * Wc[(long long)e * CC + c];
        lg[c] = acc;
    }
    __syncthreads();

    float m = -1e30f;
    for (int c = tid; c < CC; c += 256) m = fmaxf(m, lg[c]);
    red[tid] = m; __syncthreads();
    for (int st = 128; st > 0; st >>= 1) {
        if (tid < st) red[tid] = fmaxf(red[tid], red[tid + st]);
        __syncthreads();
    }
    m = red[0];
    __syncthreads();

    float sum = 0.f;
    for (int c = tid; c < CC; c += 256) {
        float e = expf(lg[c] - m);
        lg[c] = e; sum += e;
    }
    red[tid] = sum; __syncthreads();
    for (int st = 128; st > 0; st >>= 1) {
        if (tid < st) red[tid] += red[tid + st];
        __syncthreads();
    }
    float inv = 1.f / red[0];
    for (int c = tid; c < CC; c += 256)
        out[(long long)b * CC + c] = lg[c] * inv;
}

// ---------------- host orchestration ----------------------------------------
extern "C" void kernel_launch(void* const* d_in, const int* in_sizes, int n_in,
                              void* d_out, int out_size) {
    const float* x     = (const float*)d_in[0];
    const float* Wk    = (const float*)d_in[1];
    const float* Wq    = (const float*)d_in[2];
    const float* Wv    = (const float*)d_in[3];
    const float* Wconv = (const float*)d_in[4];
    const float* ln1_w = (const float*)d_in[5];
    const float* ln1_b = (const float*)d_in[6];
    const float* ln2_w = (const float*)d_in[7];
    const float* ln2_b = (const float*)d_in[8];
    const float* W1    = (const float*)d_in[9];
    const float* b1    = (const float*)d_in[10];
    const float* W2    = (const float*)d_in[11];
    const float* b2    = (const float*)d_in[12];
    const float* Wc    = (const float*)d_in[13];
    const float* bc    = (const float*)d_in[14];
    float* out = (float*)d_out;

    float *ph, *pxn, *pq, *pk, *pv, *patt, *po, *pres1, *pff;
    cudaGetSymbolAddress((void**)&ph,    g_h);
    cudaGetSymbolAddress((void**)&pxn,   g_xn);
    cudaGetSymbolAddress((void**)&pq,    g_q);
    cudaGetSymbolAddress((void**)&pk,    g_k);
    cudaGetSymbolAddress((void**)&pv,    g_v);
    cudaGetSymbolAddress((void**)&patt,  g_att);
    cudaGetSymbolAddress((void**)&po,    g_o);
    cudaGetSymbolAddress((void**)&pres1, g_res1);
    cudaGetSymbolAddress((void**)&pff,   g_ff);

    cudaMemcpyAsync(ph, x, sizeof(float) * (size_t)BS * EE,
                    cudaMemcpyDeviceToDevice);

    const float inv_scale = 1.f / sqrtf((float)SS);
    const int MT = (BS + BM - 1) / BM;  // 50 row tiles

    for (int l = 0; l < LL; l++) {
        const float* Wq_l = Wq + (long long)l * HH * EE * DHH;
        const float* Wk_l = Wk + (long long)l * HH * EE * DHH;
        const float* Wv_l = Wv + (long long)l * HH * EE * DHH;
        const float* Wcv_l = Wconv + (long long)l * EE * EE;
        const float* W1_l = W1 + (long long)l * EE * FF_;
        const float* b1_l = b1 + (long long)l * FF_;
        const float* W2_l = W2 + (long long)l * FF_ * EE;
        const float* b2_l = b2 + (long long)l * EE;

        // LN1
        layernorm_kernel<<<BS, 256>>>(ph, ln1_w + l * EE, ln1_b + l * EE, pxn);

        // Q,K,V: per-head GEMM  [BS x 768] @ [768 x 64]  (z over heads)
        {
            dim3 g(1, MT, HH);
            tc_gemm_kernel<0, false><<<g, 256>>>(pxn, Wq_l, pq, nullptr, nullptr,
                BS, DHH, EE, EE, DHH, DHH,
                0, 0, 0, (long long)EE * DHH,
                0, (long long)BS * DHH, HH, 1.f);
            tc_gemm_kernel<0, false><<<g, 256>>>(pxn, Wk_l, pk, nullptr, nullptr,
                BS, DHH, EE, EE, DHH, DHH,
                0, 0, 0, (long long)EE * DHH,
                0, (long long)BS * DHH, HH, 1.f);
            tc_gemm_kernel<0, false><<<g, 256>>>(pxn, Wv_l, pv, nullptr, nullptr,
                BS, DHH, EE, EE, DHH, DHH,
                0, 0, 0, (long long)EE * DHH,
                0, (long long)BS * DHH, HH, 1.f);
        }

        // scores = Q @ K^T * inv_scale   (batched over b,h)
        {
            dim3 g((SS + BN - 1) / BN, (SS + BM - 1) / BM, BB * HH);
            tc_gemm_kernel<0, true><<<g, 256>>>(pq, pk, patt, nullptr, nullptr,
                SS, SS, DHH, DHH, DHH, SS,
                (long long)SS * DHH, (long long)BS * DHH,
                (long long)SS * DHH, (long long)BS * DHH,
                (long long)HH * SS * SS, (long long)SS * SS, HH, inv_scale);
        }

        // softmax over last dim
        att_softmax_kernel<<<BB * HH * SS, 128>>>(patt);

        // O = att @ V  (write directly into concat-head layout [bs][h*64+d])
        {
            dim3 g(1, (SS + BM - 1) / BM, BB * HH);
            tc_gemm_kernel<0, false><<<g, 256>>>(patt, pv, po, nullptr, nullptr,
                SS, DHH, SS, SS, DHH, EE,
                (long long)HH * SS * SS, (long long)SS * SS,
                (long long)SS * DHH, (long long)BS * DHH,
                (long long)SS * EE, (long long)DHH, HH, 1.f);
        }

        // res1 = O @ Wconv + h
        {
            dim3 g(EE / BN, MT, 1);
            tc_gemm_kernel<2, false><<<g, 256>>>(po, Wcv_l, pres1, nullptr, ph,
                BS, EE, EE, EE, EE, EE,
                0, 0, 0, 0, 0, 0, 1, 1.f);
        }

        // LN2
        layernorm_kernel<<<BS, 256>>>(pres1, ln2_w + l * EE, ln2_b + l * EE, pxn);

        // FF1 = gelu(xn2 @ W1 + b1)
        {
            dim3 g(FF_ / BN, MT, 1);
            tc_gemm_kernel<1, false><<<g, 256>>>(pxn, W1_l, pff, b1_l, nullptr,
                BS, FF_, EE, EE, FF_, FF_,
                0, 0, 0, 0, 0, 0, 1, 1.f);
        }

        // h = FF1 @ W2 + b2 + res1
        {
            dim3 g(EE / BN, MT, 1);
            tc_gemm_kernel<3, false><<<g, 256>>>(pff, W2_l, ph, b2_l, pres1,
                BS, EE, FF_, FF_, EE, EE,
                0, 0, 0, 0, 0, 0, 1, 1.f);
        }
    }

    // classifier + softmax
    classifier_kernel<<<BB, 256>>>(ph, Wc, bc, out);
}